// round 3
// baseline (speedup 1.0000x reference)
#include <cuda_runtime.h>
#include <math.h>

#define N_NODES 50000
#define N_EDGES 800000
#define N_GRAPHS 64
#define EPSLN 1e-5f

// ---------------- static scratch (no allocation allowed) ----------------
__device__ __align__(128) float g_bufA[(size_t)N_NODES * 256];
__device__ __align__(128) float g_bufB[(size_t)N_NODES * 512];
__device__ __align__(128) float g_bufC[(size_t)N_NODES * 256];
__device__ __align__(128) float g_val[N_EDGES];
__device__ int   g_col[N_EDGES];
__device__ int   g_rowptr[N_NODES + 1];
__device__ int   g_cnt_in[N_NODES];
__device__ int   g_cnt_out[N_NODES];
__device__ int   g_cursor[N_NODES];
__device__ float g_innorm[N_NODES];
__device__ float g_outnorm[N_NODES];
__device__ int   g_gstart[N_GRAPHS + 1];

// ---------------- CSR build ----------------
__global__ void k_zero_counts() {
    int i = blockIdx.x * blockDim.x + threadIdx.x;
    if (i < N_NODES) { g_cnt_in[i] = 0; g_cnt_out[i] = 0; g_cursor[i] = 0; }
}

__global__ void k_hist(const int* __restrict__ src, const int* __restrict__ dst) {
    int e = blockIdx.x * blockDim.x + threadIdx.x;
    if (e < N_EDGES) {
        atomicAdd(&g_cnt_out[src[e]], 1);
        atomicAdd(&g_cnt_in[dst[e]], 1);
    }
}

__global__ void k_norms() {
    int i = blockIdx.x * blockDim.x + threadIdx.x;
    if (i < N_NODES) {
        g_outnorm[i] = rsqrtf(fmaxf((float)g_cnt_out[i], 1.0f));
        g_innorm[i]  = rsqrtf(fmaxf((float)g_cnt_in[i], 1.0f));
    }
}

// single-block exclusive scan of g_cnt_in -> g_rowptr
__global__ void k_scan() {
    __shared__ int sh[512];
    __shared__ int carry;
    int tid = threadIdx.x;
    if (tid == 0) carry = 0;
    __syncthreads();
    for (int base = 0; base < N_NODES; base += 512) {
        int i = base + tid;
        int v = (i < N_NODES) ? g_cnt_in[i] : 0;
        sh[tid] = v;
        __syncthreads();
        #pragma unroll
        for (int off = 1; off < 512; off <<= 1) {
            int t = (tid >= off) ? sh[tid - off] : 0;
            __syncthreads();
            sh[tid] += t;
            __syncthreads();
        }
        int incl = sh[tid];
        if (i < N_NODES) g_rowptr[i] = carry + incl - v;
        __syncthreads();
        if (tid == 511) carry += sh[511];
        __syncthreads();
    }
    if (tid == 0) g_rowptr[N_NODES] = carry;
}

__global__ void k_scatter(const int* __restrict__ src, const int* __restrict__ dst,
                          const float* __restrict__ w) {
    int e = blockIdx.x * blockDim.x + threadIdx.x;
    if (e < N_EDGES) {
        int d = dst[e];
        int p = atomicAdd(&g_cursor[d], 1);
        int slot = g_rowptr[d] + p;
        int s = src[e];
        g_col[slot] = s;
        g_val[slot] = w[e] * g_outnorm[s];
    }
}

// ---------------- SpMM: dst-stationary, warp per node ----------------
template<int DIM, bool EPI>  // EPI: multiply in_norm[dst] + relu
__global__ void k_spmm(const float* __restrict__ x, float* __restrict__ out) {
    int warp = threadIdx.x >> 5, lane = threadIdx.x & 31;
    int v = blockIdx.x * (blockDim.x >> 5) + warp;
    if (v >= N_NODES) return;
    int e0 = g_rowptr[v], e1 = g_rowptr[v + 1];
    float4 a0 = make_float4(0.f, 0.f, 0.f, 0.f);
    float4 a1 = make_float4(0.f, 0.f, 0.f, 0.f);
    const float4* xv = reinterpret_cast<const float4*>(x);
    for (int e = e0; e < e1; ++e) {
        int s = g_col[e];
        float a = g_val[e];
        float4 xa = xv[(size_t)s * (DIM / 4) + lane];
        a0.x += a * xa.x; a0.y += a * xa.y; a0.z += a * xa.z; a0.w += a * xa.w;
        if (DIM == 256) {
            float4 xb = xv[(size_t)s * (DIM / 4) + lane + 32];
            a1.x += a * xb.x; a1.y += a * xb.y; a1.z += a * xb.z; a1.w += a * xb.w;
        }
    }
    float sc = EPI ? g_innorm[v] : 1.0f;
    float4 o0, o1;
    if (EPI) {
        o0.x = fmaxf(a0.x * sc, 0.f); o0.y = fmaxf(a0.y * sc, 0.f);
        o0.z = fmaxf(a0.z * sc, 0.f); o0.w = fmaxf(a0.w * sc, 0.f);
        o1.x = fmaxf(a1.x * sc, 0.f); o1.y = fmaxf(a1.y * sc, 0.f);
        o1.z = fmaxf(a1.z * sc, 0.f); o1.w = fmaxf(a1.w * sc, 0.f);
    } else { o0 = a0; o1 = a1; }
    float4* ov = reinterpret_cast<float4*>(out);
    ov[(size_t)v * (DIM / 4) + lane] = o0;
    if (DIM == 256) ov[(size_t)v * (DIM / 4) + lane + 32] = o1;
}

// ---------------- GEMM: C[M x 256] = A[M x K] @ B[K x 256] ----------------
// 128x128 block tile, BK=16, 256 threads, 8x8 per-thread micro-tile.
// EPI: 0 = plain store, 1 = row-scale by g_innorm + relu.
template<int EPI>
__global__ void __launch_bounds__(256, 2)
k_gemm(const float* __restrict__ A, const float* __restrict__ B,
       float* __restrict__ C, int M, int K, int lda, int ldc) {
    __shared__ float As[16][132];
    __shared__ float Bs[16][128];
    int tid = threadIdx.x;
    int ty = tid >> 4, tx = tid & 15;
    int rowBase = blockIdx.x * 128;
    int colBase = blockIdx.y * 128;
    float acc[8][8];
    #pragma unroll
    for (int i = 0; i < 8; i++)
        #pragma unroll
        for (int j = 0; j < 8; j++) acc[i][j] = 0.f;

    for (int kt = 0; kt < K; kt += 16) {
        #pragma unroll
        for (int l = 0; l < 2; l++) {
            int f = tid + l * 256;          // 512 float4s of A tile
            int r = f >> 2, c4 = f & 3;
            int row = rowBase + r;
            float4 av = make_float4(0.f, 0.f, 0.f, 0.f);
            if (row < M)
                av = *reinterpret_cast<const float4*>(A + (size_t)row * lda + kt + c4 * 4);
            As[c4 * 4 + 0][r] = av.x;
            As[c4 * 4 + 1][r] = av.y;
            As[c4 * 4 + 2][r] = av.z;
            As[c4 * 4 + 3][r] = av.w;
        }
        #pragma unroll
        for (int l = 0; l < 2; l++) {
            int f = tid + l * 256;          // 512 float4s of B tile
            int r = f >> 5, c4 = f & 31;
            *reinterpret_cast<float4*>(&Bs[r][c4 * 4]) =
                *reinterpret_cast<const float4*>(B + (size_t)(kt + r) * 256 + colBase + c4 * 4);
        }
        __syncthreads();
        #pragma unroll
        for (int k = 0; k < 16; k++) {
            float4 af0 = *reinterpret_cast<const float4*>(&As[k][ty * 8]);
            float4 af1 = *reinterpret_cast<const float4*>(&As[k][ty * 8 + 4]);
            float4 bf0 = *reinterpret_cast<const float4*>(&Bs[k][tx * 8]);
            float4 bf1 = *reinterpret_cast<const float4*>(&Bs[k][tx * 8 + 4]);
            float ar[8] = {af0.x, af0.y, af0.z, af0.w, af1.x, af1.y, af1.z, af1.w};
            float br[8] = {bf0.x, bf0.y, bf0.z, bf0.w, bf1.x, bf1.y, bf1.z, bf1.w};
            #pragma unroll
            for (int i = 0; i < 8; i++)
                #pragma unroll
                for (int j = 0; j < 8; j++)
                    acc[i][j] = fmaf(ar[i], br[j], acc[i][j]);
        }
        __syncthreads();
    }

    #pragma unroll
    for (int i = 0; i < 8; i++) {
        int row = rowBase + ty * 8 + i;
        if (row >= M) break;
        float sc = (EPI == 1) ? g_innorm[row] : 1.0f;
        #pragma unroll
        for (int j0 = 0; j0 < 2; j0++) {
            float4 o;
            float v0 = acc[i][j0 * 4 + 0], v1 = acc[i][j0 * 4 + 1];
            float v2 = acc[i][j0 * 4 + 2], v3 = acc[i][j0 * 4 + 3];
            if (EPI == 1) {
                o.x = fmaxf(v0 * sc, 0.f); o.y = fmaxf(v1 * sc, 0.f);
                o.z = fmaxf(v2 * sc, 0.f); o.w = fmaxf(v3 * sc, 0.f);
            } else { o.x = v0; o.y = v1; o.z = v2; o.w = v3; }
            *reinterpret_cast<float4*>(C + (size_t)row * ldc + colBase + tx * 8 + j0 * 4) = o;
        }
    }
}

// ---------------- LayerNorm + relu, row per block ----------------
__global__ void k_ln_relu(const float* __restrict__ in, const float* __restrict__ gamma,
                          const float* __restrict__ beta, float* __restrict__ out) {
    __shared__ float ws[8], ws2[8];
    int row = blockIdx.x, c = threadIdx.x;
    float v = in[(size_t)row * 256 + c];
    float s = v, s2 = v * v;
    #pragma unroll
    for (int off = 16; off > 0; off >>= 1) {
        s  += __shfl_xor_sync(0xffffffffu, s, off);
        s2 += __shfl_xor_sync(0xffffffffu, s2, off);
    }
    int wid = c >> 5, lane = c & 31;
    if (lane == 0) { ws[wid] = s; ws2[wid] = s2; }
    __syncthreads();
    float tot = 0.f, tot2 = 0.f;
    #pragma unroll
    for (int i = 0; i < 8; i++) { tot += ws[i]; tot2 += ws2[i]; }
    float mu = tot * (1.0f / 256.0f);
    float var = tot2 * (1.0f / 256.0f) - mu * mu;
    float o = (v - mu) * rsqrtf(var + EPSLN) * gamma[c] + beta[c];
    out[(size_t)row * 512 + c] = fmaxf(o, 0.f);
}

// ---------------- readout (graph_ids sorted) ----------------
__global__ void k_gstart(const int* __restrict__ gid) {
    int i = blockIdx.x * blockDim.x + threadIdx.x;
    if (i >= N_NODES) return;
    int g = gid[i];
    int gp = (i == 0) ? -1 : gid[i - 1];
    for (int gg = gp + 1; gg <= g; ++gg) g_gstart[gg] = i;
    if (i == N_NODES - 1)
        for (int gg = g + 1; gg <= N_GRAPHS; ++gg) g_gstart[gg] = N_NODES;
}

__global__ void k_readout(const float* __restrict__ x3, float* __restrict__ out) {
    int g = blockIdx.x, c = threadIdx.x;
    int s = g_gstart[g], e = g_gstart[g + 1];
    float a0 = 0.f, a1 = 0.f, a2 = 0.f, a3 = 0.f;
    int r = s;
    for (; r + 4 <= e; r += 4) {
        a0 += x3[(size_t)(r + 0) * 256 + c];
        a1 += x3[(size_t)(r + 1) * 256 + c];
        a2 += x3[(size_t)(r + 2) * 256 + c];
        a3 += x3[(size_t)(r + 3) * 256 + c];
    }
    for (; r < e; ++r) a0 += x3[(size_t)r * 256 + c];
    out[(size_t)g * 256 + c] = (a0 + a1) + (a2 + a3);
}

// ---------------- launch ----------------
extern "C" void kernel_launch(void* const* d_in, const int* in_sizes, int n_in,
                              void* d_out, int out_size) {
    const float* x     = (const float*)d_in[0];
    const float* w     = (const float*)d_in[1];
    const float* W1    = (const float*)d_in[2];
    const float* Wfc   = (const float*)d_in[3];
    const float* gamma = (const float*)d_in[4];
    const float* beta  = (const float*)d_in[5];
    const float* W2    = (const float*)d_in[6];
    const float* W3    = (const float*)d_in[7];
    const int*   src   = (const int*)d_in[8];
    const int*   dst   = (const int*)d_in[9];
    const int*   gid   = (const int*)d_in[10];
    float* out = (float*)d_out;

    float *bufA, *bufB, *bufC;
    cudaGetSymbolAddress((void**)&bufA, g_bufA);
    cudaGetSymbolAddress((void**)&bufB, g_bufB);
    cudaGetSymbolAddress((void**)&bufC, g_bufC);

    const int TB = 256;
    int nodeBlocks = (N_NODES + TB - 1) / TB;
    int edgeBlocks = (N_EDGES + TB - 1) / TB;
    int spmmBlocks = (N_NODES + 7) / 8;
    dim3 gemmGrid((N_NODES + 127) / 128, 2);

    // graph preprocessing
    k_zero_counts<<<nodeBlocks, TB>>>();
    k_hist<<<edgeBlocks, TB>>>(src, dst);
    k_norms<<<nodeBlocks, TB>>>();
    k_scan<<<1, 512>>>();
    k_scatter<<<edgeBlocks, TB>>>(src, dst, w);

    // conv1: agg(x) -> @W1 -> *in_norm, relu -> x1 (bufB cols 0:256)
    k_spmm<128, false><<<spmmBlocks, TB>>>(x, bufA);
    k_gemm<1><<<gemmGrid, TB>>>(bufA, W1, bufB, N_NODES, 128, 128, 512);

    // fc branch: x@Wfc -> LN -> relu -> f1 (bufB cols 256:512)
    k_gemm<0><<<gemmGrid, TB>>>(x, Wfc, bufC, N_NODES, 128, 128, 256);
    k_ln_relu<<<N_NODES, TB>>>(bufC, gamma, beta, bufB + 256);

    // conv2: (x1f1)@W2 -> agg -> *in_norm, relu -> x2 (bufC)
    k_gemm<0><<<gemmGrid, TB>>>(bufB, W2, bufA, N_NODES, 512, 512, 256);
    k_spmm<256, true><<<spmmBlocks, TB>>>(bufA, bufC);

    // conv3: agg(x2) -> @W3 -> *in_norm, relu -> x3 (bufC)
    k_spmm<256, false><<<spmmBlocks, TB>>>(bufC, bufA);
    k_gemm<1><<<gemmGrid, TB>>>(bufA, W3, bufC, N_NODES, 256, 256, 256);

    // readout
    k_gstart<<<nodeBlocks, TB>>>(gid);
    k_readout<<<N_GRAPHS, TB>>>(bufC, out);
}

// round 7
// speedup vs baseline: 1.1211x; 1.1211x over previous
#include <cuda_runtime.h>
#include <math.h>

#define N_NODES 50000
#define N_EDGES 800000
#define N_GRAPHS 64
#define EPSLN 1e-5f
#define SCAN_NBLK 196  // ceil(50000/256)

// ---------------- static scratch (no allocation allowed) ----------------
__device__ __align__(128) float g_bufA[(size_t)N_NODES * 256];
__device__ __align__(128) float g_bufB[(size_t)N_NODES * 512];
__device__ __align__(128) float g_bufC[(size_t)N_NODES * 256];
__device__ __align__(128) float g_val[N_EDGES];
__device__ int   g_col[N_EDGES];
__device__ int   g_rowptr[N_NODES + 1];
__device__ int   g_cnt_in[N_NODES];
__device__ int   g_cnt_out[N_NODES];
__device__ int   g_cursor[N_NODES];
__device__ float g_innorm[N_NODES];
__device__ float g_outnorm[N_NODES];
__device__ int   g_gstart[N_GRAPHS + 1];
__device__ int   g_blocksum[256];

// ---------------- helpers ----------------
__device__ __forceinline__ void cp_async16(void* smem, const void* gmem) {
    unsigned saddr = (unsigned)__cvta_generic_to_shared(smem);
    asm volatile("cp.async.cg.shared.global [%0], [%1], 16;\n" :: "r"(saddr), "l"(gmem));
}
__device__ __forceinline__ void cp_async_commit() {
    asm volatile("cp.async.commit_group;\n");
}
__device__ __forceinline__ void cp_async_wait_all() {
    asm volatile("cp.async.wait_group 0;\n");
}

// ---------------- CSR build ----------------
__global__ void k_zero_counts() {
    int i = blockIdx.x * blockDim.x + threadIdx.x;
    if (i < N_NODES) { g_cnt_in[i] = 0; g_cnt_out[i] = 0; g_cursor[i] = 0; }
}

__global__ void k_hist(const int* __restrict__ src, const int* __restrict__ dst) {
    int e = blockIdx.x * blockDim.x + threadIdx.x;
    if (e < N_EDGES) {
        atomicAdd(&g_cnt_out[src[e]], 1);
        atomicAdd(&g_cnt_in[dst[e]], 1);
    }
}

__global__ void k_norms() {
    int i = blockIdx.x * blockDim.x + threadIdx.x;
    if (i < N_NODES) {
        g_outnorm[i] = rsqrtf(fmaxf((float)g_cnt_out[i], 1.0f));
        g_innorm[i]  = rsqrtf(fmaxf((float)g_cnt_in[i], 1.0f));
    }
}

// 3-phase parallel exclusive scan of g_cnt_in -> g_rowptr
__global__ void k_scan1() {
    __shared__ int sh[256];
    int i = blockIdx.x * 256 + threadIdx.x;
    sh[threadIdx.x] = (i < N_NODES) ? g_cnt_in[i] : 0;
    __syncthreads();
    #pragma unroll
    for (int off = 128; off > 0; off >>= 1) {
        if (threadIdx.x < off) sh[threadIdx.x] += sh[threadIdx.x + off];
        __syncthreads();
    }
    if (threadIdx.x == 0) g_blocksum[blockIdx.x] = sh[0];
}

__global__ void k_scan2() {
    __shared__ int sh[256];
    int t = threadIdx.x;
    int v = (t < SCAN_NBLK) ? g_blocksum[t] : 0;
    sh[t] = v;
    __syncthreads();
    #pragma unroll
    for (int off = 1; off < 256; off <<= 1) {
        int tv = (t >= off) ? sh[t - off] : 0;
        __syncthreads();
        sh[t] += tv;
        __syncthreads();
    }
    if (t < SCAN_NBLK) g_blocksum[t] = sh[t] - v;  // exclusive
    if (t == 0) g_rowptr[N_NODES] = N_EDGES;
}

__global__ void k_scan3() {
    __shared__ int sh[256];
    int i = blockIdx.x * 256 + threadIdx.x;
    int t = threadIdx.x;
    int v = (i < N_NODES) ? g_cnt_in[i] : 0;
    sh[t] = v;
    __syncthreads();
    #pragma unroll
    for (int off = 1; off < 256; off <<= 1) {
        int tv = (t >= off) ? sh[t - off] : 0;
        __syncthreads();
        sh[t] += tv;
        __syncthreads();
    }
    if (i < N_NODES) g_rowptr[i] = sh[t] - v + g_blocksum[blockIdx.x];
}

__global__ void k_scatter(const int* __restrict__ src, const int* __restrict__ dst,
                          const float* __restrict__ w) {
    int e = blockIdx.x * blockDim.x + threadIdx.x;
    if (e < N_EDGES) {
        int d = dst[e];
        int p = atomicAdd(&g_cursor[d], 1);
        int slot = g_rowptr[d] + p;
        int s = src[e];
        g_col[slot] = s;
        g_val[slot] = w[e] * g_outnorm[s];
    }
}

// ---------------- SpMM: dst-stationary, warp per node ----------------
template<int DIM, bool EPI>  // EPI: multiply in_norm[dst] + relu
__global__ void k_spmm(const float* __restrict__ x, float* __restrict__ out) {
    int warp = threadIdx.x >> 5, lane = threadIdx.x & 31;
    int v = blockIdx.x * (blockDim.x >> 5) + warp;
    if (v >= N_NODES) return;
    int e0 = g_rowptr[v], e1 = g_rowptr[v + 1];
    float4 a0 = make_float4(0.f, 0.f, 0.f, 0.f);
    float4 a1 = make_float4(0.f, 0.f, 0.f, 0.f);
    const float4* xv = reinterpret_cast<const float4*>(x);
    for (int e = e0; e < e1; ++e) {
        int s = g_col[e];
        float a = g_val[e];
        float4 xa = xv[(size_t)s * (DIM / 4) + lane];
        a0.x += a * xa.x; a0.y += a * xa.y; a0.z += a * xa.z; a0.w += a * xa.w;
        if (DIM == 256) {
            float4 xb = xv[(size_t)s * (DIM / 4) + lane + 32];
            a1.x += a * xb.x; a1.y += a * xb.y; a1.z += a * xb.z; a1.w += a * xb.w;
        }
    }
    float sc = EPI ? g_innorm[v] : 1.0f;
    float4 o0, o1;
    if (EPI) {
        o0.x = fmaxf(a0.x * sc, 0.f); o0.y = fmaxf(a0.y * sc, 0.f);
        o0.z = fmaxf(a0.z * sc, 0.f); o0.w = fmaxf(a0.w * sc, 0.f);
        o1.x = fmaxf(a1.x * sc, 0.f); o1.y = fmaxf(a1.y * sc, 0.f);
        o1.z = fmaxf(a1.z * sc, 0.f); o1.w = fmaxf(a1.w * sc, 0.f);
    } else { o0 = a0; o1 = a1; }
    float4* ov = reinterpret_cast<float4*>(out);
    ov[(size_t)v * (DIM / 4) + lane] = o0;
    if (DIM == 256) ov[(size_t)v * (DIM / 4) + lane + 32] = o1;
}

// ---------------- GEMM: C[M x 256] = A[M x K] @ B[K x 256] ----------------
// 128x128 tile, BK=16, 256 threads, 8x8 micro-tile, double-buffered:
// B staged via cp.async, A staged via registers (transposed store).
template<int EPI>
__global__ void __launch_bounds__(256, 2)
k_gemm(const float* __restrict__ A, const float* __restrict__ B,
       float* __restrict__ C, int M, int K, int lda, int ldc) {
    __shared__ float As[2][16][132];
    __shared__ float Bs[2][16][128];
    int tid = threadIdx.x;
    int ty = tid >> 4, tx = tid & 15;
    int rowBase = blockIdx.x * 128;
    int colBase = blockIdx.y * 128;

    // A tile mapping: 512 float4s, thread handles f=tid and f=tid+256
    int ra0 = tid >> 2,          ca0 = tid & 3;
    int ra1 = (tid + 256) >> 2,  ca1 = tid & 3;
    // B tile mapping: 512 float4s
    int rb0 = tid >> 5,          cb  = tid & 31;
    int rb1 = (tid + 256) >> 5;

    float acc[8][8];
    #pragma unroll
    for (int i = 0; i < 8; i++)
        #pragma unroll
        for (int j = 0; j < 8; j++) acc[i][j] = 0.f;

    const int NT = K / 16;
    const float4 f4z = make_float4(0.f, 0.f, 0.f, 0.f);
    int row0 = rowBase + ra0, row1 = rowBase + ra1;

    // prologue: fill buffer 0
    {
        float4 a0 = (row0 < M) ? *reinterpret_cast<const float4*>(A + (size_t)row0 * lda + ca0 * 4) : f4z;
        float4 a1 = (row1 < M) ? *reinterpret_cast<const float4*>(A + (size_t)row1 * lda + ca1 * 4) : f4z;
        As[0][ca0 * 4 + 0][ra0] = a0.x; As[0][ca0 * 4 + 1][ra0] = a0.y;
        As[0][ca0 * 4 + 2][ra0] = a0.z; As[0][ca0 * 4 + 3][ra0] = a0.w;
        As[0][ca1 * 4 + 0][ra1] = a1.x; As[0][ca1 * 4 + 1][ra1] = a1.y;
        As[0][ca1 * 4 + 2][ra1] = a1.z; As[0][ca1 * 4 + 3][ra1] = a1.w;
        cp_async16(&Bs[0][rb0][cb * 4], B + (size_t)rb0 * 256 + colBase + cb * 4);
        cp_async16(&Bs[0][rb1][cb * 4], B + (size_t)rb1 * 256 + colBase + cb * 4);
        cp_async_commit();
        cp_async_wait_all();
        __syncthreads();
    }

    for (int it = 0; it < NT; ++it) {
        int s = it & 1;
        float4 a0, a1;
        if (it + 1 < NT) {
            int kt = (it + 1) * 16;
            cp_async16(&Bs[s ^ 1][rb0][cb * 4], B + (size_t)(kt + rb0) * 256 + colBase + cb * 4);
            cp_async16(&Bs[s ^ 1][rb1][cb * 4], B + (size_t)(kt + rb1) * 256 + colBase + cb * 4);
            cp_async_commit();
            a0 = (row0 < M) ? *reinterpret_cast<const float4*>(A + (size_t)row0 * lda + kt + ca0 * 4) : f4z;
            a1 = (row1 < M) ? *reinterpret_cast<const float4*>(A + (size_t)row1 * lda + kt + ca1 * 4) : f4z;
        }
        #pragma unroll
        for (int k = 0; k < 16; k++) {
            float4 af0 = *reinterpret_cast<const float4*>(&As[s][k][ty * 8]);
            float4 af1 = *reinterpret_cast<const float4*>(&As[s][k][ty * 8 + 4]);
            float4 bf0 = *reinterpret_cast<const float4*>(&Bs[s][k][tx * 8]);
            float4 bf1 = *reinterpret_cast<const float4*>(&Bs[s][k][tx * 8 + 4]);
            float ar[8] = {af0.x, af0.y, af0.z, af0.w, af1.x, af1.y, af1.z, af1.w};
            float br[8] = {bf0.x, bf0.y, bf0.z, bf0.w, bf1.x, bf1.y, bf1.z, bf1.w};
            #pragma unroll
            for (int i = 0; i < 8; i++)
                #pragma unroll
                for (int j = 0; j < 8; j++)
                    acc[i][j] = fmaf(ar[i], br[j], acc[i][j]);
        }
        if (it + 1 < NT) {
            As[s ^ 1][ca0 * 4 + 0][ra0] = a0.x; As[s ^ 1][ca0 * 4 + 1][ra0] = a0.y;
            As[s ^ 1][ca0 * 4 + 2][ra0] = a0.z; As[s ^ 1][ca0 * 4 + 3][ra0] = a0.w;
            As[s ^ 1][ca1 * 4 + 0][ra1] = a1.x; As[s ^ 1][ca1 * 4 + 1][ra1] = a1.y;
            As[s ^ 1][ca1 * 4 + 2][ra1] = a1.z; As[s ^ 1][ca1 * 4 + 3][ra1] = a1.w;
            cp_async_wait_all();
            __syncthreads();
        }
    }

    #pragma unroll
    for (int i = 0; i < 8; i++) {
        int row = rowBase + ty * 8 + i;
        if (row >= M) break;
        float sc = (EPI == 1) ? g_innorm[row] : 1.0f;
        #pragma unroll
        for (int j0 = 0; j0 < 2; j0++) {
            float4 o;
            float v0 = acc[i][j0 * 4 + 0], v1 = acc[i][j0 * 4 + 1];
            float v2 = acc[i][j0 * 4 + 2], v3 = acc[i][j0 * 4 + 3];
            if (EPI == 1) {
                o.x = fmaxf(v0 * sc, 0.f); o.y = fmaxf(v1 * sc, 0.f);
                o.z = fmaxf(v2 * sc, 0.f); o.w = fmaxf(v3 * sc, 0.f);
            } else { o.x = v0; o.y = v1; o.z = v2; o.w = v3; }
            *reinterpret_cast<float4*>(C + (size_t)row * ldc + colBase + tx * 8 + j0 * 4) = o;
        }
    }
}

// ---------------- LayerNorm + relu, row per block ----------------
__global__ void k_ln_relu(const float* __restrict__ in, const float* __restrict__ gamma,
                          const float* __restrict__ beta, float* __restrict__ out) {
    __shared__ float ws[8], ws2[8];
    int row = blockIdx.x, c = threadIdx.x;
    float v = in[(size_t)row * 256 + c];
    float s = v, s2 = v * v;
    #pragma unroll
    for (int off = 16; off > 0; off >>= 1) {
        s  += __shfl_xor_sync(0xffffffffu, s, off);
        s2 += __shfl_xor_sync(0xffffffffu, s2, off);
    }
    int wid = c >> 5, lane = c & 31;
    if (lane == 0) { ws[wid] = s; ws2[wid] = s2; }
    __syncthreads();
    float tot = 0.f, tot2 = 0.f;
    #pragma unroll
    for (int i = 0; i < 8; i++) { tot += ws[i]; tot2 += ws2[i]; }
    float mu = tot * (1.0f / 256.0f);
    float var = tot2 * (1.0f / 256.0f) - mu * mu;
    float o = (v - mu) * rsqrtf(var + EPSLN) * gamma[c] + beta[c];
    out[(size_t)row * 512 + c] = fmaxf(o, 0.f);
}

// ---------------- readout (graph_ids sorted) ----------------
__global__ void k_gstart(const int* __restrict__ gid) {
    int i = blockIdx.x * blockDim.x + threadIdx.x;
    if (i >= N_NODES) return;
    int g = gid[i];
    int gp = (i == 0) ? -1 : gid[i - 1];
    for (int gg = gp + 1; gg <= g; ++gg) g_gstart[gg] = i;
    if (i == N_NODES - 1)
        for (int gg = g + 1; gg <= N_GRAPHS; ++gg) g_gstart[gg] = N_NODES;
}

__global__ void k_readout(const float* __restrict__ x3, float* __restrict__ out) {
    int g = blockIdx.x, c = threadIdx.x;
    int s = g_gstart[g], e = g_gstart[g + 1];
    float a0 = 0.f, a1 = 0.f, a2 = 0.f, a3 = 0.f;
    int r = s;
    for (; r + 4 <= e; r += 4) {
        a0 += x3[(size_t)(r + 0) * 256 + c];
        a1 += x3[(size_t)(r + 1) * 256 + c];
        a2 += x3[(size_t)(r + 2) * 256 + c];
        a3 += x3[(size_t)(r + 3) * 256 + c];
    }
    for (; r < e; ++r) a0 += x3[(size_t)r * 256 + c];
    out[(size_t)g * 256 + c] = (a0 + a1) + (a2 + a3);
}

// ---------------- launch ----------------
extern "C" void kernel_launch(void* const* d_in, const int* in_sizes, int n_in,
                              void* d_out, int out_size) {
    const float* x     = (const float*)d_in[0];
    const float* w     = (const float*)d_in[1];
    const float* W1    = (const float*)d_in[2];
    const float* Wfc   = (const float*)d_in[3];
    const float* gamma = (const float*)d_in[4];
    const float* beta  = (const float*)d_in[5];
    const float* W2    = (const float*)d_in[6];
    const float* W3    = (const float*)d_in[7];
    const int*   src   = (const int*)d_in[8];
    const int*   dst   = (const int*)d_in[9];
    const int*   gid   = (const int*)d_in[10];
    float* out = (float*)d_out;

    float *bufA, *bufB, *bufC;
    cudaGetSymbolAddress((void**)&bufA, g_bufA);
    cudaGetSymbolAddress((void**)&bufB, g_bufB);
    cudaGetSymbolAddress((void**)&bufC, g_bufC);

    const int TB = 256;
    int nodeBlocks = (N_NODES + TB - 1) / TB;
    int edgeBlocks = (N_EDGES + TB - 1) / TB;
    int spmmBlocks = (N_NODES + 7) / 8;
    dim3 gemmGrid((N_NODES + 127) / 128, 2);

    // graph preprocessing
    k_zero_counts<<<nodeBlocks, TB>>>();
    k_hist<<<edgeBlocks, TB>>>(src, dst);
    k_norms<<<nodeBlocks, TB>>>();
    k_scan1<<<SCAN_NBLK, 256>>>();
    k_scan2<<<1, 256>>>();
    k_scan3<<<SCAN_NBLK, 256>>>();
    k_scatter<<<edgeBlocks, TB>>>(src, dst, w);

    // conv1: agg(x) -> @W1 -> *in_norm, relu -> x1 (bufB cols 0:256)
    k_spmm<128, false><<<spmmBlocks, TB>>>(x, bufA);
    k_gemm<1><<<gemmGrid, TB>>>(bufA, W1, bufB, N_NODES, 128, 128, 512);

    // fc branch: x@Wfc -> LN -> relu -> f1 (bufB cols 256:512)
    k_gemm<0><<<gemmGrid, TB>>>(x, Wfc, bufC, N_NODES, 128, 128, 256);
    k_ln_relu<<<N_NODES, TB>>>(bufC, gamma, beta, bufB + 256);

    // conv2: (x1f1)@W2 -> agg -> *in_norm, relu -> x2 (bufC)
    k_gemm<0><<<gemmGrid, TB>>>(bufB, W2, bufA, N_NODES, 512, 512, 256);
    k_spmm<256, true><<<spmmBlocks, TB>>>(bufA, bufC);

    // conv3: agg(x2) -> @W3 -> *in_norm, relu -> x3 (bufC)
    k_spmm<256, false><<<spmmBlocks, TB>>>(bufC, bufA);
    k_gemm<1><<<gemmGrid, TB>>>(bufA, W3, bufC, N_NODES, 256, 256, 256);

    // readout
    k_gstart<<<nodeBlocks, TB>>>(gid);
    k_readout<<<N_GRAPHS, TB>>>(bufC, out);
}

// round 8
// speedup vs baseline: 2.6006x; 2.3196x over previous
#include <cuda_runtime.h>
#include <cuda_fp16.h>
#include <math.h>

#define N_NODES 50000
#define N_EDGES 800000
#define N_GRAPHS 64
#define EPSLN 1e-5f
#define SCAN_NBLK 196  // ceil(50000/256)

// ---------------- static scratch (no allocation allowed) ----------------
__device__ __align__(128) float  g_bufC[(size_t)N_NODES * 256];   // fp32: fc pre-LN, then x3
__device__ __align__(128) __half g_xh[(size_t)N_NODES * 128];
__device__ __align__(128) __half g_aggh[(size_t)N_NODES * 256];   // spmm1 out (128-stride) & spmm3 out (256)
__device__ __align__(128) __half g_bufBh[(size_t)N_NODES * 512];  // x1 || f1
__device__ __align__(128) __half g_bufAh[(size_t)N_NODES * 256];  // gemm2 out
__device__ __align__(128) __half g_x2h[(size_t)N_NODES * 256];    // spmm2 out
__device__ __half g_W1h[128 * 256];
__device__ __half g_Wfch[128 * 256];
__device__ __half g_W2h[512 * 256];
__device__ __half g_W3h[256 * 256];
__device__ __align__(128) float g_val[N_EDGES];
__device__ int   g_col[N_EDGES];
__device__ int   g_rowptr[N_NODES + 1];
__device__ int   g_cnt_in[N_NODES];
__device__ int   g_cnt_out[N_NODES];
__device__ int   g_cursor[N_NODES];
__device__ float g_innorm[N_NODES];
__device__ float g_outnorm[N_NODES];
__device__ int   g_gstart[N_GRAPHS + 1];
__device__ int   g_blocksum[256];

// ---------------- helpers ----------------
__device__ __forceinline__ void cp_async16(void* smem, const void* gmem) {
    unsigned saddr = (unsigned)__cvta_generic_to_shared(smem);
    asm volatile("cp.async.cg.shared.global [%0], [%1], 16;\n" :: "r"(saddr), "l"(gmem));
}
__device__ __forceinline__ void cp_async16_zfill(void* smem, const void* gmem, bool valid) {
    unsigned saddr = (unsigned)__cvta_generic_to_shared(smem);
    int sz = valid ? 16 : 0;
    asm volatile("cp.async.cg.shared.global [%0], [%1], 16, %2;\n" :: "r"(saddr), "l"(gmem), "r"(sz));
}
__device__ __forceinline__ void cp_async_commit() { asm volatile("cp.async.commit_group;\n"); }
__device__ __forceinline__ void cp_async_wait0() { asm volatile("cp.async.wait_group 0;\n"); }
__device__ __forceinline__ void cp_async_wait1() { asm volatile("cp.async.wait_group 1;\n"); }

__device__ __forceinline__ void ldsm_x4(unsigned& r0, unsigned& r1, unsigned& r2, unsigned& r3, unsigned addr) {
    asm volatile("ldmatrix.sync.aligned.m8n8.x4.shared.b16 {%0,%1,%2,%3}, [%4];"
                 : "=r"(r0), "=r"(r1), "=r"(r2), "=r"(r3) : "r"(addr));
}
__device__ __forceinline__ void ldsm_x4t(unsigned& r0, unsigned& r1, unsigned& r2, unsigned& r3, unsigned addr) {
    asm volatile("ldmatrix.sync.aligned.m8n8.x4.trans.shared.b16 {%0,%1,%2,%3}, [%4];"
                 : "=r"(r0), "=r"(r1), "=r"(r2), "=r"(r3) : "r"(addr));
}
__device__ __forceinline__ void mma16816(float& c0, float& c1, float& c2, float& c3,
                                         unsigned a0, unsigned a1, unsigned a2, unsigned a3,
                                         unsigned b0, unsigned b1) {
    asm volatile("mma.sync.aligned.m16n8k16.row.col.f32.f16.f16.f32 "
                 "{%0,%1,%2,%3}, {%4,%5,%6,%7}, {%8,%9}, {%0,%1,%2,%3};"
                 : "+f"(c0), "+f"(c1), "+f"(c2), "+f"(c3)
                 : "r"(a0), "r"(a1), "r"(a2), "r"(a3), "r"(b0), "r"(b1));
}

// ---------------- CSR build ----------------
__global__ void k_zero_counts() {
    int i = blockIdx.x * blockDim.x + threadIdx.x;
    if (i < N_NODES) { g_cnt_in[i] = 0; g_cnt_out[i] = 0; g_cursor[i] = 0; }
}
__global__ void k_hist(const int* __restrict__ src, const int* __restrict__ dst) {
    int e = blockIdx.x * blockDim.x + threadIdx.x;
    if (e < N_EDGES) {
        atomicAdd(&g_cnt_out[src[e]], 1);
        atomicAdd(&g_cnt_in[dst[e]], 1);
    }
}
__global__ void k_norms() {
    int i = blockIdx.x * blockDim.x + threadIdx.x;
    if (i < N_NODES) {
        g_outnorm[i] = rsqrtf(fmaxf((float)g_cnt_out[i], 1.0f));
        g_innorm[i]  = rsqrtf(fmaxf((float)g_cnt_in[i], 1.0f));
    }
}
__global__ void k_scan1() {
    __shared__ int sh[256];
    int i = blockIdx.x * 256 + threadIdx.x;
    sh[threadIdx.x] = (i < N_NODES) ? g_cnt_in[i] : 0;
    __syncthreads();
    #pragma unroll
    for (int off = 128; off > 0; off >>= 1) {
        if (threadIdx.x < off) sh[threadIdx.x] += sh[threadIdx.x + off];
        __syncthreads();
    }
    if (threadIdx.x == 0) g_blocksum[blockIdx.x] = sh[0];
}
__global__ void k_scan2() {
    __shared__ int sh[256];
    int t = threadIdx.x;
    int v = (t < SCAN_NBLK) ? g_blocksum[t] : 0;
    sh[t] = v;
    __syncthreads();
    #pragma unroll
    for (int off = 1; off < 256; off <<= 1) {
        int tv = (t >= off) ? sh[t - off] : 0;
        __syncthreads();
        sh[t] += tv;
        __syncthreads();
    }
    if (t < SCAN_NBLK) g_blocksum[t] = sh[t] - v;
    if (t == 0) g_rowptr[N_NODES] = N_EDGES;
}
__global__ void k_scan3() {
    __shared__ int sh[256];
    int i = blockIdx.x * 256 + threadIdx.x;
    int t = threadIdx.x;
    int v = (i < N_NODES) ? g_cnt_in[i] : 0;
    sh[t] = v;
    __syncthreads();
    #pragma unroll
    for (int off = 1; off < 256; off <<= 1) {
        int tv = (t >= off) ? sh[t - off] : 0;
        __syncthreads();
        sh[t] += tv;
        __syncthreads();
    }
    if (i < N_NODES) g_rowptr[i] = sh[t] - v + g_blocksum[blockIdx.x];
}
__global__ void k_scatter(const int* __restrict__ src, const int* __restrict__ dst,
                          const float* __restrict__ w) {
    int e = blockIdx.x * blockDim.x + threadIdx.x;
    if (e < N_EDGES) {
        int d = dst[e];
        int p = atomicAdd(&g_cursor[d], 1);
        int slot = g_rowptr[d] + p;
        int s = src[e];
        g_col[slot] = s;
        g_val[slot] = w[e] * g_outnorm[s];
    }
}

// ---------------- fp32 -> fp16 convert ----------------
__global__ void k_f2h(const float* __restrict__ in, __half* __restrict__ out, int n2) {
    int i = blockIdx.x * blockDim.x + threadIdx.x;  // over half2 pairs
    if (i < n2) {
        float2 f = reinterpret_cast<const float2*>(in)[i];
        reinterpret_cast<__half2*>(out)[i] = __floats2half2_rn(f.x, f.y);
    }
}

// ---------------- SpMM (half in, fp32 accum, half out) ----------------
template<int DIM, bool EPI>
__global__ void k_spmmh(const __half* __restrict__ x, __half* __restrict__ out) {
    int warp = threadIdx.x >> 5, lane = threadIdx.x & 31;
    int v = blockIdx.x * (blockDim.x >> 5) + warp;
    if (v >= N_NODES) return;
    int e0 = g_rowptr[v], e1 = g_rowptr[v + 1];
    if (DIM == 128) {
        float a0 = 0.f, a1 = 0.f, a2 = 0.f, a3 = 0.f;
        const uint2* xv = reinterpret_cast<const uint2*>(x);
        for (int e = e0; e < e1; ++e) {
            int s = g_col[e];
            float w = g_val[e];
            uint2 p = xv[(size_t)s * 32 + lane];
            float2 f0 = __half22float2(*reinterpret_cast<__half2*>(&p.x));
            float2 f1 = __half22float2(*reinterpret_cast<__half2*>(&p.y));
            a0 = fmaf(w, f0.x, a0); a1 = fmaf(w, f0.y, a1);
            a2 = fmaf(w, f1.x, a2); a3 = fmaf(w, f1.y, a3);
        }
        if (EPI) {
            float sc = g_innorm[v];
            a0 = fmaxf(a0 * sc, 0.f); a1 = fmaxf(a1 * sc, 0.f);
            a2 = fmaxf(a2 * sc, 0.f); a3 = fmaxf(a3 * sc, 0.f);
        }
        uint2 o;
        *reinterpret_cast<__half2*>(&o.x) = __floats2half2_rn(a0, a1);
        *reinterpret_cast<__half2*>(&o.y) = __floats2half2_rn(a2, a3);
        reinterpret_cast<uint2*>(out)[(size_t)v * 32 + lane] = o;
    } else {
        float a[8];
        #pragma unroll
        for (int i = 0; i < 8; i++) a[i] = 0.f;
        const uint4* xv = reinterpret_cast<const uint4*>(x);
        for (int e = e0; e < e1; ++e) {
            int s = g_col[e];
            float w = g_val[e];
            uint4 p = xv[(size_t)s * 32 + lane];
            float2 f0 = __half22float2(*reinterpret_cast<__half2*>(&p.x));
            float2 f1 = __half22float2(*reinterpret_cast<__half2*>(&p.y));
            float2 f2 = __half22float2(*reinterpret_cast<__half2*>(&p.z));
            float2 f3 = __half22float2(*reinterpret_cast<__half2*>(&p.w));
            a[0] = fmaf(w, f0.x, a[0]); a[1] = fmaf(w, f0.y, a[1]);
            a[2] = fmaf(w, f1.x, a[2]); a[3] = fmaf(w, f1.y, a[3]);
            a[4] = fmaf(w, f2.x, a[4]); a[5] = fmaf(w, f2.y, a[5]);
            a[6] = fmaf(w, f3.x, a[6]); a[7] = fmaf(w, f3.y, a[7]);
        }
        if (EPI) {
            float sc = g_innorm[v];
            #pragma unroll
            for (int i = 0; i < 8; i++) a[i] = fmaxf(a[i] * sc, 0.f);
        }
        uint4 o;
        *reinterpret_cast<__half2*>(&o.x) = __floats2half2_rn(a[0], a[1]);
        *reinterpret_cast<__half2*>(&o.y) = __floats2half2_rn(a[2], a[3]);
        *reinterpret_cast<__half2*>(&o.z) = __floats2half2_rn(a[4], a[5]);
        *reinterpret_cast<__half2*>(&o.w) = __floats2half2_rn(a[6], a[7]);
        reinterpret_cast<uint4*>(out)[(size_t)v * 32 + lane] = o;
    }
}

// ---------------- fp16 tensor-core GEMM ----------------
// C[M x 256] = A[M x K](half) @ B[K x 256](half)
// 128x128 tile, BK=32, 256 thr, 8 warps of 64x32, m16n8k16 mma, fp32 accum.
// EPI: 0 = fp32 plain, 1 = fp32 innorm+relu, 2 = half innorm+relu, 3 = half plain.
template<int EPI>
__global__ void __launch_bounds__(256, 2)
k_gemm16(const __half* __restrict__ A, const __half* __restrict__ B,
         void* __restrict__ Cout, int M, int K, int lda, int ldc) {
    __shared__ __align__(16) __half Ash[2][128][40];
    __shared__ __align__(16) __half Bsh[2][32][136];

    int tid = threadIdx.x;
    int wid = tid >> 5, lane = tid & 31;
    int wm = wid >> 2, wn = wid & 3;          // warp grid 2 x 4
    int rowBase = blockIdx.x * 128;
    int colBase = blockIdx.y * 128;

    // cp.async mappings
    int arow0 = tid >> 2,          ac0 = (tid & 3) * 8;   // A: 512 chunks of 8 halves
    int arow1 = (tid + 256) >> 2,  ac1 = (tid & 3) * 8;
    int brow0 = tid >> 4,          bc  = (tid & 15) * 8;  // B: 512 chunks
    int brow1 = (tid + 256) >> 4;

    float acc[4][4][4];
    #pragma unroll
    for (int i = 0; i < 4; i++)
        #pragma unroll
        for (int j = 0; j < 4; j++)
            #pragma unroll
            for (int c = 0; c < 4; c++) acc[i][j][c] = 0.f;

    const int NT = K >> 5;

    auto issueA = [&](int s, int kt) {
        bool v0 = (rowBase + arow0) < M, v1 = (rowBase + arow1) < M;
        const __half* p0 = A + (size_t)(v0 ? rowBase + arow0 : 0) * lda + kt + ac0;
        const __half* p1 = A + (size_t)(v1 ? rowBase + arow1 : 0) * lda + kt + ac1;
        cp_async16_zfill(&Ash[s][arow0][ac0], p0, v0);
        cp_async16_zfill(&Ash[s][arow1][ac1], p1, v1);
    };
    auto issueB = [&](int s, int kt) {
        cp_async16(&Bsh[s][brow0][bc], B + (size_t)(kt + brow0) * 256 + colBase + bc);
        cp_async16(&Bsh[s][brow1][bc], B + (size_t)(kt + brow1) * 256 + colBase + bc);
    };

    issueA(0, 0); issueB(0, 0); cp_async_commit();

    unsigned sbaseA = (unsigned)__cvta_generic_to_shared(&Ash[0][0][0]);
    unsigned sbaseB = (unsigned)__cvta_generic_to_shared(&Bsh[0][0][0]);
    const unsigned strideA = 128 * 40 * 2;   // bytes per A buffer
    const unsigned strideB = 32 * 136 * 2;
    int l15 = lane & 15, l16sel = (lane & 16) ? 8 : 0;

    for (int it = 0; it < NT; ++it) {
        int s = it & 1;
        if (it + 1 < NT) {
            issueA(s ^ 1, (it + 1) << 5); issueB(s ^ 1, (it + 1) << 5);
            cp_async_commit();
            cp_async_wait1();
        } else {
            cp_async_wait0();
        }
        __syncthreads();

        #pragma unroll
        for (int ks = 0; ks < 2; ++ks) {
            unsigned a[4][4];
            #pragma unroll
            for (int mt = 0; mt < 4; ++mt) {
                int row = wm * 64 + mt * 16 + l15;
                unsigned addr = sbaseA + s * strideA + (row * 40 + ks * 16 + l16sel) * 2;
                ldsm_x4(a[mt][0], a[mt][1], a[mt][2], a[mt][3], addr);
            }
            unsigned b[2][4];
            #pragma unroll
            for (int np = 0; np < 2; ++np) {
                int krow = ks * 16 + l15;
                int col = wn * 32 + np * 16 + l16sel;
                unsigned addr = sbaseB + s * strideB + (krow * 136 + col) * 2;
                ldsm_x4t(b[np][0], b[np][1], b[np][2], b[np][3], addr);
            }
            #pragma unroll
            for (int mt = 0; mt < 4; ++mt)
                #pragma unroll
                for (int nt = 0; nt < 4; ++nt) {
                    unsigned b0 = (nt & 1) ? b[nt >> 1][2] : b[nt >> 1][0];
                    unsigned b1 = (nt & 1) ? b[nt >> 1][3] : b[nt >> 1][1];
                    mma16816(acc[mt][nt][0], acc[mt][nt][1], acc[mt][nt][2], acc[mt][nt][3],
                             a[mt][0], a[mt][1], a[mt][2], a[mt][3], b0, b1);
                }
        }
        __syncthreads();
    }

    // epilogue
    int g = lane >> 2, t = lane & 3;
    #pragma unroll
    for (int mt = 0; mt < 4; ++mt) {
        int row_lo = rowBase + wm * 64 + mt * 16 + g;
        int row_hi = row_lo + 8;
        bool vlo = row_lo < M, vhi = row_hi < M;
        float slo = 1.f, shi = 1.f;
        if (EPI == 1 || EPI == 2) {
            if (vlo) slo = g_innorm[row_lo];
            if (vhi) shi = g_innorm[row_hi];
        }
        #pragma unroll
        for (int nt = 0; nt < 4; ++nt) {
            int col = colBase + wn * 32 + nt * 8 + 2 * t;
            float c0 = acc[mt][nt][0], c1 = acc[mt][nt][1];
            float c2 = acc[mt][nt][2], c3 = acc[mt][nt][3];
            if (EPI == 1 || EPI == 2) {
                c0 = fmaxf(c0 * slo, 0.f); c1 = fmaxf(c1 * slo, 0.f);
                c2 = fmaxf(c2 * shi, 0.f); c3 = fmaxf(c3 * shi, 0.f);
            }
            if (EPI == 0 || EPI == 1) {
                float* C = (float*)Cout;
                if (vlo) *reinterpret_cast<float2*>(C + (size_t)row_lo * ldc + col) = make_float2(c0, c1);
                if (vhi) *reinterpret_cast<float2*>(C + (size_t)row_hi * ldc + col) = make_float2(c2, c3);
            } else {
                __half* C = (__half*)Cout;
                if (vlo) *reinterpret_cast<__half2*>(C + (size_t)row_lo * ldc + col) = __floats2half2_rn(c0, c1);
                if (vhi) *reinterpret_cast<__half2*>(C + (size_t)row_hi * ldc + col) = __floats2half2_rn(c2, c3);
            }
        }
    }
}

// ---------------- LayerNorm + relu (fp32 in, half out) ----------------
__global__ void k_ln_relu(const float* __restrict__ in, const float* __restrict__ gamma,
                          const float* __restrict__ beta, __half* __restrict__ out) {
    __shared__ float ws[8], ws2[8];
    int row = blockIdx.x, c = threadIdx.x;
    float v = in[(size_t)row * 256 + c];
    float s = v, s2 = v * v;
    #pragma unroll
    for (int off = 16; off > 0; off >>= 1) {
        s  += __shfl_xor_sync(0xffffffffu, s, off);
        s2 += __shfl_xor_sync(0xffffffffu, s2, off);
    }
    int wid = c >> 5, lane = c & 31;
    if (lane == 0) { ws[wid] = s; ws2[wid] = s2; }
    __syncthreads();
    float tot = 0.f, tot2 = 0.f;
    #pragma unroll
    for (int i = 0; i < 8; i++) { tot += ws[i]; tot2 += ws2[i]; }
    float mu = tot * (1.0f / 256.0f);
    float var = tot2 * (1.0f / 256.0f) - mu * mu;
    float o = (v - mu) * rsqrtf(var + EPSLN) * gamma[c] + beta[c];
    out[(size_t)row * 512 + c] = __float2half_rn(fmaxf(o, 0.f));
}

// ---------------- readout (graph_ids sorted) ----------------
__global__ void k_gstart(const int* __restrict__ gid) {
    int i = blockIdx.x * blockDim.x + threadIdx.x;
    if (i >= N_NODES) return;
    int g = gid[i];
    int gp = (i == 0) ? -1 : gid[i - 1];
    for (int gg = gp + 1; gg <= g; ++gg) g_gstart[gg] = i;
    if (i == N_NODES - 1)
        for (int gg = g + 1; gg <= N_GRAPHS; ++gg) g_gstart[gg] = N_NODES;
}
__global__ void k_readout(const float* __restrict__ x3, float* __restrict__ out) {
    int g = blockIdx.x, c = threadIdx.x;
    int s = g_gstart[g], e = g_gstart[g + 1];
    float a0 = 0.f, a1 = 0.f, a2 = 0.f, a3 = 0.f;
    int r = s;
    for (; r + 4 <= e; r += 4) {
        a0 += x3[(size_t)(r + 0) * 256 + c];
        a1 += x3[(size_t)(r + 1) * 256 + c];
        a2 += x3[(size_t)(r + 2) * 256 + c];
        a3 += x3[(size_t)(r + 3) * 256 + c];
    }
    for (; r < e; ++r) a0 += x3[(size_t)r * 256 + c];
    out[(size_t)g * 256 + c] = (a0 + a1) + (a2 + a3);
}

// ---------------- launch ----------------
extern "C" void kernel_launch(void* const* d_in, const int* in_sizes, int n_in,
                              void* d_out, int out_size) {
    const float* x     = (const float*)d_in[0];
    const float* w     = (const float*)d_in[1];
    const float* W1    = (const float*)d_in[2];
    const float* Wfc   = (const float*)d_in[3];
    const float* gamma = (const float*)d_in[4];
    const float* beta  = (const float*)d_in[5];
    const float* W2    = (const float*)d_in[6];
    const float* W3    = (const float*)d_in[7];
    const int*   src   = (const int*)d_in[8];
    const int*   dst   = (const int*)d_in[9];
    const int*   gid   = (const int*)d_in[10];
    float* out = (float*)d_out;

    float *bufC;
    __half *xh, *aggh, *bufBh, *bufAh, *x2h, *W1h, *Wfch, *W2h, *W3h;
    cudaGetSymbolAddress((void**)&bufC, g_bufC);
    cudaGetSymbolAddress((void**)&xh, g_xh);
    cudaGetSymbolAddress((void**)&aggh, g_aggh);
    cudaGetSymbolAddress((void**)&bufBh, g_bufBh);
    cudaGetSymbolAddress((void**)&bufAh, g_bufAh);
    cudaGetSymbolAddress((void**)&x2h, g_x2h);
    cudaGetSymbolAddress((void**)&W1h, g_W1h);
    cudaGetSymbolAddress((void**)&Wfch, g_Wfch);
    cudaGetSymbolAddress((void**)&W2h, g_W2h);
    cudaGetSymbolAddress((void**)&W3h, g_W3h);

    const int TB = 256;
    int nodeBlocks = (N_NODES + TB - 1) / TB;
    int edgeBlocks = (N_EDGES + TB - 1) / TB;
    int spmmBlocks = (N_NODES + 7) / 8;
    dim3 gemmGrid((N_NODES + 127) / 128, 2);

    // graph preprocessing
    k_zero_counts<<<nodeBlocks, TB>>>();
    k_hist<<<edgeBlocks, TB>>>(src, dst);
    k_norms<<<nodeBlocks, TB>>>();
    k_scan1<<<SCAN_NBLK, 256>>>();
    k_scan2<<<1, 256>>>();
    k_scan3<<<SCAN_NBLK, 256>>>();
    k_scatter<<<edgeBlocks, TB>>>(src, dst, w);

    // fp16 conversions
    k_f2h<<<(N_NODES * 64 + TB - 1) / TB, TB>>>(x, xh, N_NODES * 64);       // 6.4M elems / 2
    k_f2h<<<(16384 + TB - 1) / TB, TB>>>(W1, W1h, 16384);
    k_f2h<<<(16384 + TB - 1) / TB, TB>>>(Wfc, Wfch, 16384);
    k_f2h<<<(65536 + TB - 1) / TB, TB>>>(W2, W2h, 65536);
    k_f2h<<<(32768 + TB - 1) / TB, TB>>>(W3, W3h, 32768);

    // conv1: agg(x) -> @W1 -> *in_norm, relu -> x1 (half, bufBh cols 0:256)
    k_spmmh<128, false><<<spmmBlocks, TB>>>(xh, aggh);
    k_gemm16<2><<<gemmGrid, TB>>>(aggh, W1h, bufBh, N_NODES, 128, 128, 512);

    // fc branch: x@Wfc -> LN -> relu -> f1 (half, bufBh cols 256:512)
    k_gemm16<0><<<gemmGrid, TB>>>(xh, Wfch, bufC, N_NODES, 128, 128, 256);
    k_ln_relu<<<N_NODES, TB>>>(bufC, gamma, beta, bufBh + 256);

    // conv2: (x1f1)@W2 -> agg -> *in_norm, relu -> x2 (half)
    k_gemm16<3><<<gemmGrid, TB>>>(bufBh, W2h, bufAh, N_NODES, 512, 512, 256);
    k_spmmh<256, true><<<spmmBlocks, TB>>>(bufAh, x2h);

    // conv3: agg(x2) -> @W3 -> *in_norm, relu -> x3 (fp32 bufC)
    k_spmmh<256, false><<<spmmBlocks, TB>>>(x2h, aggh);
    k_gemm16<1><<<gemmGrid, TB>>>(aggh, W3h, bufC, N_NODES, 256, 256, 256);

    // readout
    k_gstart<<<nodeBlocks, TB>>>(gid);
    k_readout<<<N_GRAPHS, TB>>>(bufC, out);
}